// round 2
// baseline (speedup 1.0000x reference)
#include <cuda_runtime.h>

#define BQ    32      // queries per batch
#define BD    512     // docs per batch
#define EDIM  300     // embedding dim
#define NK    11      // RBF kernels
#define DCH   128     // doc rows per SMEM chunk
#define RSD   132     // deT row stride (floats): 128 + 4 pad (2-way store conflicts max)
#define RSQ   36      // qeT row stride (floats): 32 + 4 pad
#define NTH   256
#define NCHUNK (BD / DCH)

__device__ __constant__ float c_mu[NK] =
    {1.0f, 0.9f, 0.7f, 0.5f, 0.3f, 0.1f, -0.1f, -0.3f, -0.5f, -0.7f, -0.9f};
// -1/(2*sigma^2): sigma0 = 1e-4 -> -5e7 ; sigma = 0.1 -> -50
__device__ __constant__ float c_ce[NK] =
    {-5.0e7f, -50.f, -50.f, -50.f, -50.f, -50.f, -50.f, -50.f, -50.f, -50.f, -50.f};

__device__ __forceinline__ float warp_sum(float v) {
    v += __shfl_xor_sync(0xffffffffu, v, 16);
    v += __shfl_xor_sync(0xffffffffu, v, 8);
    v += __shfl_xor_sync(0xffffffffu, v, 4);
    v += __shfl_xor_sync(0xffffffffu, v, 2);
    v += __shfl_xor_sync(0xffffffffu, v, 1);
    return v;
}

__global__ __launch_bounds__(NTH, 1)
void knrm_kernel(const int* __restrict__ qt,
                 const int* __restrict__ dt,
                 const float* __restrict__ emb,
                 const float* __restrict__ fcw,
                 const float* __restrict__ fcb,
                 float* __restrict__ out)
{
    extern __shared__ float sm[];
    float* deT = sm;                        // [EDIM][RSD] transposed doc tile
    float* qeT = deT + EDIM * RSD;          // [EDIM][RSQ] transposed query tile
    float* rq  = qeT + EDIM * RSQ;          // [BQ]  1/(||q||+eps)
    float* wq  = rq + BQ;                   // [BQ]  mask
    float* rd  = wq + BQ;                   // [DCH]
    float* wd  = rd + DCH;                  // [DCH]
    float* qk  = wd + DCH;                  // [BQ][NK] kernel-pool accumulators

    const int b    = blockIdx.x;
    const int tid  = threadIdx.x;
    const int lane = tid & 31;
    const int warp = tid >> 5;

    for (int i = tid; i < BQ * NK; i += NTH) qk[i] = 0.0f;

    // ---- load 32 query embedding rows, transposed, + norms/masks (4 rows/warp) ----
    #pragma unroll
    for (int r = 0; r < BQ / 8; ++r) {
        const int q   = warp * (BQ / 8) + r;
        const int tok = qt[b * BQ + q];
        const float4* src = reinterpret_cast<const float4*>(emb) + (size_t)tok * (EDIM / 4);
        float* dst = qeT + q;
        float ssq = 0.0f;
        float4 v;

        v = src[lane];
        ssq += v.x*v.x + v.y*v.y + v.z*v.z + v.w*v.w;
        { const int e0 = lane * 4;
          dst[(e0+0)*RSQ] = v.x; dst[(e0+1)*RSQ] = v.y;
          dst[(e0+2)*RSQ] = v.z; dst[(e0+3)*RSQ] = v.w; }

        v = src[lane + 32];
        ssq += v.x*v.x + v.y*v.y + v.z*v.z + v.w*v.w;
        { const int e0 = (lane + 32) * 4;
          dst[(e0+0)*RSQ] = v.x; dst[(e0+1)*RSQ] = v.y;
          dst[(e0+2)*RSQ] = v.z; dst[(e0+3)*RSQ] = v.w; }

        if (lane < 11) {  // 75 float4 per row: 32 + 32 + 11
            v = src[lane + 64];
            ssq += v.x*v.x + v.y*v.y + v.z*v.z + v.w*v.w;
            const int e0 = (lane + 64) * 4;
            dst[(e0+0)*RSQ] = v.x; dst[(e0+1)*RSQ] = v.y;
            dst[(e0+2)*RSQ] = v.z; dst[(e0+3)*RSQ] = v.w;
        }
        ssq = warp_sum(ssq);
        if (lane == 0) {
            rq[q] = 1.0f / (sqrtf(ssq) + 1e-13f);
            wq[q] = (tok > 0) ? 1.0f : 0.0f;
        }
    }

    // compute-thread mapping: 8 q-groups x 32 d-groups, 4x4 micro-tile each
    const int tq  = tid & 7;
    const int tdg = tid >> 3;
    const float* qp = qeT + tq * 4;
    const float* dp = deT + tdg * 4;

    float acc[4][NK];
    #pragma unroll
    for (int i = 0; i < 4; ++i)
        #pragma unroll
        for (int k = 0; k < NK; ++k) acc[i][k] = 0.0f;

    float rqv[4], wqv[4];

    for (int ch = 0; ch < NCHUNK; ++ch) {
        __syncthreads();   // previous chunk's readers done before overwrite

        // ---- load 128 doc rows, transposed, + norms/masks (16 rows/warp) ----
        #pragma unroll 2
        for (int r = 0; r < DCH / 8; ++r) {
            const int dloc = warp * (DCH / 8) + r;
            const int tok  = dt[b * BD + ch * DCH + dloc];
            const float4* src = reinterpret_cast<const float4*>(emb) + (size_t)tok * (EDIM / 4);
            float* dst = deT + dloc;
            float ssq = 0.0f;
            float4 v;

            v = src[lane];
            ssq += v.x*v.x + v.y*v.y + v.z*v.z + v.w*v.w;
            { const int e0 = lane * 4;
              dst[(e0+0)*RSD] = v.x; dst[(e0+1)*RSD] = v.y;
              dst[(e0+2)*RSD] = v.z; dst[(e0+3)*RSD] = v.w; }

            v = src[lane + 32];
            ssq += v.x*v.x + v.y*v.y + v.z*v.z + v.w*v.w;
            { const int e0 = (lane + 32) * 4;
              dst[(e0+0)*RSD] = v.x; dst[(e0+1)*RSD] = v.y;
              dst[(e0+2)*RSD] = v.z; dst[(e0+3)*RSD] = v.w; }

            if (lane < 11) {
                v = src[lane + 64];
                ssq += v.x*v.x + v.y*v.y + v.z*v.z + v.w*v.w;
                const int e0 = (lane + 64) * 4;
                dst[(e0+0)*RSD] = v.x; dst[(e0+1)*RSD] = v.y;
                dst[(e0+2)*RSD] = v.z; dst[(e0+3)*RSD] = v.w;
            }
            ssq = warp_sum(ssq);
            if (lane == 0) {
                rd[dloc] = 1.0f / (sqrtf(ssq) + 1e-13f);
                wd[dloc] = (tok > 0) ? 1.0f : 0.0f;
            }
        }
        __syncthreads();

        if (ch == 0) {
            #pragma unroll
            for (int i = 0; i < 4; ++i) {
                rqv[i] = rq[tq * 4 + i];
                wqv[i] = wq[tq * 4 + i];
            }
        }

        // ---- 4x4 rank-1-update GEMM over E=300 ----
        float mm[4][4];
        #pragma unroll
        for (int i = 0; i < 4; ++i)
            #pragma unroll
            for (int j = 0; j < 4; ++j) mm[i][j] = 0.0f;

        const float* qpe = qp;
        const float* dpe = dp;
        #pragma unroll 4
        for (int e = 0; e < EDIM; ++e) {
            const float4 qv = *reinterpret_cast<const float4*>(qpe);
            const float4 dv = *reinterpret_cast<const float4*>(dpe);
            qpe += RSQ; dpe += RSD;
            const float qa[4] = {qv.x, qv.y, qv.z, qv.w};
            const float da[4] = {dv.x, dv.y, dv.z, dv.w};
            #pragma unroll
            for (int i = 0; i < 4; ++i)
                #pragma unroll
                for (int j = 0; j < 4; ++j)
                    mm[i][j] = fmaf(qa[i], da[j], mm[i][j]);
        }

        // ---- RBF epilogue: m = cos (via norm scalars), masked accumulate ----
        float rdv[4], wdv[4];
        #pragma unroll
        for (int j = 0; j < 4; ++j) {
            rdv[j] = rd[tdg * 4 + j];
            wdv[j] = wd[tdg * 4 + j];
        }
        #pragma unroll
        for (int i = 0; i < 4; ++i) {
            #pragma unroll
            for (int j = 0; j < 4; ++j) {
                const float m = mm[i][j] * (rqv[i] * rdv[j]);
                const float w = wqv[i] * wdv[j];
                #pragma unroll
                for (int k = 0; k < NK; ++k) {
                    const float d0 = m - c_mu[k];
                    acc[i][k] = fmaf(w, __expf(d0 * d0 * c_ce[k]), acc[i][k]);
                }
            }
        }
    }

    // ---- reduce acc over d-groups: shfl (4-way in-warp) + shared atomics (8 warps) ----
    #pragma unroll
    for (int i = 0; i < 4; ++i) {
        #pragma unroll
        for (int k = 0; k < NK; ++k) {
            float v = acc[i][k];
            v += __shfl_down_sync(0xffffffffu, v, 16);
            v += __shfl_down_sync(0xffffffffu, v, 8);
            if (lane < 8) atomicAdd(&qk[(tq * 4 + i) * NK + k], v);
        }
    }
    __syncthreads();

    // ---- log-pool over Q, FC, write score ----
    if (tid < BQ) {
        float s = 0.0f;
        #pragma unroll
        for (int k = 0; k < NK; ++k)
            s += fcw[k] * 0.01f * logf(fmaxf(qk[tid * NK + k], 1e-10f));
        s = warp_sum(s);
        if (lane == 0) out[b] = s + fcb[0];
    }
}

extern "C" void kernel_launch(void* const* d_in, const int* in_sizes, int n_in,
                              void* d_out, int out_size)
{
    const int*   qt  = (const int*)d_in[0];
    const int*   dt  = (const int*)d_in[1];
    const float* emb = (const float*)d_in[2];
    const float* fcw = (const float*)d_in[3];
    const float* fcb = (const float*)d_in[4];
    float* out = (float*)d_out;

    const int B = in_sizes[0] / BQ;   // 256

    const size_t smem = (size_t)(EDIM * RSD + EDIM * RSQ + 2 * BQ + 2 * DCH + BQ * NK)
                        * sizeof(float);   // 204,288 B
    cudaFuncSetAttribute(knrm_kernel,
                         cudaFuncAttributeMaxDynamicSharedMemorySize, (int)smem);
    knrm_kernel<<<B, NTH, smem>>>(qt, dt, emb, fcw, fcb, out);
}